// round 4
// baseline (speedup 1.0000x reference)
#include <cuda_runtime.h>
#include <cstdint>

#define NTH 256

// shared memory layout (float offsets), per CTA total 27008 floats = 105.5 KB
#define XF  0        // x fragments: 2 blk * 32 step * 32 lane * 8 = 16384
#define HF  16384    // h fragments: 2 blk * 8 step * 32 lane * 8 = 4096
#define W1S 20480    // w1 slabs: 2 buf * 16*72 = 2304
#define W2S 22784    // w2 slabs: 2 buf * 8*264 = 4224
#define SMEM_FLOATS 27008
#define SMEM_BYTES  (SMEM_FLOATS * 4)

__device__ __forceinline__ uint32_t f32_tf32(float x) {
    uint32_t u; asm("cvt.rna.tf32.f32 %0, %1;" : "=r"(u) : "f"(x)); return u;
}
__device__ __forceinline__ float tf32f(float x) { return __uint_as_float(f32_tf32(x)); }
__device__ __forceinline__ float4 cvt4(float4 v) {
    return make_float4(tf32f(v.x), tf32f(v.y), tf32f(v.z), tf32f(v.w));
}
__device__ __forceinline__ void mma_tf32(float c[4], uint32_t a0, uint32_t a1, uint32_t a2, uint32_t a3,
                                         uint32_t b0, uint32_t b1) {
    asm volatile(
        "mma.sync.aligned.m16n8k8.row.col.f32.tf32.tf32.f32 "
        "{%0,%1,%2,%3}, {%4,%5,%6,%7}, {%8,%9}, {%0,%1,%2,%3};\n"
        : "+f"(c[0]), "+f"(c[1]), "+f"(c[2]), "+f"(c[3])
        : "r"(a0), "r"(a1), "r"(a2), "r"(a3), "r"(b0), "r"(b1));
}
__device__ __forceinline__ float silu(float v) { return v / (1.0f + expf(-v)); }

// fragment-major h store (slot rotation: slot = mt ^ (g & 1), matching reader)
__device__ __forceinline__ void hf_put(float* sm, int r, int cl, float v) {
    int blk  = r >> 5;
    int mt   = (r >> 4) & 1;
    int g_   = r & 7;
    int rh   = (r >> 3) & 1;
    int step = cl >> 3;
    int cc   = cl & 7;
    int tgp  = cc & 3;
    int hi   = cc >> 2;
    int lanep = (g_ << 2) | tgp;
    int slot  = mt ^ (g_ & 1);
    sm[HF + ((blk * 8 + step) * 32 + lanep) * 8 + slot * 4 + hi * 2 + rh] = tf32f(v);
}

__global__ __launch_bounds__(NTH, 2)
void mlp_mma_v3(const float* __restrict__ x,
                const float* __restrict__ w1,
                const float* __restrict__ w2,
                float* __restrict__ out) {
    extern __shared__ float sm[];

    const int tid  = threadIdx.x;
    const int wid  = tid >> 5;
    const int lane = tid & 31;
    const int g    = lane >> 2;
    const int tg   = lane & 3;
    const int head = blockIdx.y;
    const int n0   = blockIdx.x * 64;

    const int wm = wid >> 2;      // 0..1  (32-row block, both GEMMs)
    const int wn = wid & 3;       // 0..3
    const int rot = g & 1;

    // ---------------- stage x[64x256] into fragment-major layout ----------------
    {
        const float* xb = x + ((size_t)head * 8192 + n0) * 256;
        #pragma unroll
        for (int j = 0; j < 16; j++) {
            int f  = tid + j * NTH;      // 0..4095 float4 index
            int m  = f >> 6;             // 0..63
            int c4 = f & 63;
            float4 v = *(const float4*)(xb + (size_t)m * 256 + c4 * 4);
            int blk = m >> 5, mt = (m >> 4) & 1, gg = m & 7, rh = (m >> 3) & 1;
            int c = c4 * 4;
            int step = c >> 3, hi = (c & 7) >> 2;
            int slot = mt ^ (gg & 1);
            int base = XF + ((blk * 32 + step) * 32 + gg * 4) * 8 + slot * 4 + hi * 2 + rh;
            sm[base]      = tf32f(v.x);
            sm[base + 8]  = tf32f(v.y);
            sm[base + 16] = tf32f(v.z);
            sm[base + 24] = tf32f(v.w);
        }
    }

    const float* w1h = w1 + (size_t)head * 256 * 1024;
    const float* w2h = w2 + (size_t)head * 1024 * 256;

    float acc2[2][8][4];
    #pragma unroll
    for (int mt = 0; mt < 2; mt++)
        #pragma unroll
        for (int nt = 0; nt < 8; nt++)
            #pragma unroll
            for (int r = 0; r < 4; r++) acc2[mt][nt][r] = 0.0f;

    // staging indices
    const int kr1 = tid >> 4, c41 = tid & 15;        // w1 slab: 16k x 64n
    const int kr2 = tid >> 6, c42 = tid & 63;        // w2 slab: 8k x 256n (x2 per thread)

    __syncthreads();

    for (int ic = 0; ic < 16; ic++) {
        const int ic0 = ic * 64;

        // ================= GEMM1: z[64x64] = x[64x256] @ w1[:, ic0:ic0+64) =================
        float acc1[2][2][4];
        #pragma unroll
        for (int mt = 0; mt < 2; mt++)
            #pragma unroll
            for (int nt = 0; nt < 2; nt++)
                #pragma unroll
                for (int r = 0; r < 4; r++) acc1[mt][nt][r] = 0.0f;

        // preload slab s=0
        {
            float4 v = *(const float4*)(w1h + (size_t)kr1 * 1024 + ic0 + c41 * 4);
            *(float4*)(sm + W1S + kr1 * 72 + c41 * 4) = cvt4(v);
        }
        __syncthreads();

        #pragma unroll
        for (int s = 0; s < 16; s++) {
            const int buf = s & 1;
            float4 p;
            if (s < 15)
                p = *(const float4*)(w1h + (size_t)((s + 1) * 16 + kr1) * 1024 + ic0 + c41 * 4);
            const float* wb = sm + W1S + buf * 1152;
            #pragma unroll
            for (int kk = 0; kk < 2; kk++) {
                const float* ab = sm + XF + ((wm * 32 + s * 2 + kk) * 32 + lane) * 8;
                float4 A0 = *(const float4*)(ab + ((0 ^ rot) << 2));
                float4 A1 = *(const float4*)(ab + ((1 ^ rot) << 2));
                #pragma unroll
                for (int nt = 0; nt < 2; nt++) {
                    int ci = (kk * 8 + tg) * 72 + wn * 16 + nt * 8 + g;
                    uint32_t b0 = __float_as_uint(wb[ci]);
                    uint32_t b1 = __float_as_uint(wb[ci + 4 * 72]);
                    mma_tf32(acc1[0][nt], __float_as_uint(A0.x), __float_as_uint(A0.y),
                             __float_as_uint(A0.z), __float_as_uint(A0.w), b0, b1);
                    mma_tf32(acc1[1][nt], __float_as_uint(A1.x), __float_as_uint(A1.y),
                             __float_as_uint(A1.z), __float_as_uint(A1.w), b0, b1);
                }
            }
            if (s < 15)
                *(float4*)(sm + W1S + (buf ^ 1) * 1152 + kr1 * 72 + c41 * 4) = cvt4(p);
            __syncthreads();
        }

        // ---- preload W2 slab t=0 (overlaps silu) ----
        {
            #pragma unroll
            for (int j = 0; j < 2; j++) {
                int kr = kr2 + j * 4;
                float4 v = *(const float4*)(w2h + (size_t)(ic0 + kr) * 256 + c42 * 4);
                *(float4*)(sm + W2S + kr * 264 + c42 * 4) = cvt4(v);
            }
        }

        // ---- silu -> h fragments ----
        #pragma unroll
        for (int mt = 0; mt < 2; mt++)
            #pragma unroll
            for (int nt = 0; nt < 2; nt++) {
                int r0  = wm * 32 + mt * 16 + g;
                int cl0 = wn * 16 + nt * 8 + 2 * tg;
                hf_put(sm, r0,     cl0,     silu(acc1[mt][nt][0]));
                hf_put(sm, r0,     cl0 + 1, silu(acc1[mt][nt][1]));
                hf_put(sm, r0 + 8, cl0,     silu(acc1[mt][nt][2]));
                hf_put(sm, r0 + 8, cl0 + 1, silu(acc1[mt][nt][3]));
            }
        __syncthreads();

        // ================= GEMM2: o[64x256] += h[64x64] @ w2[ic0:ic0+64, :) =================
        #pragma unroll
        for (int t = 0; t < 8; t++) {
            const int buf = t & 1;
            float4 q0, q1;
            if (t < 7) {
                q0 = *(const float4*)(w2h + (size_t)(ic0 + (t + 1) * 8 + kr2) * 256 + c42 * 4);
                q1 = *(const float4*)(w2h + (size_t)(ic0 + (t + 1) * 8 + kr2 + 4) * 256 + c42 * 4);
            }
            const float* wb = sm + W2S + buf * 2112;
            const float* ab = sm + HF + ((wm * 8 + t) * 32 + lane) * 8;
            float4 A0 = *(const float4*)(ab + ((0 ^ rot) << 2));
            float4 A1 = *(const float4*)(ab + ((1 ^ rot) << 2));
            uint32_t a00 = __float_as_uint(A0.x), a01 = __float_as_uint(A0.y),
                     a02 = __float_as_uint(A0.z), a03 = __float_as_uint(A0.w);
            uint32_t a10 = __float_as_uint(A1.x), a11 = __float_as_uint(A1.y),
                     a12 = __float_as_uint(A1.z), a13 = __float_as_uint(A1.w);
            #pragma unroll
            for (int nt = 0; nt < 8; nt++) {
                int ci = tg * 264 + wn * 64 + nt * 8 + g;
                uint32_t b0 = __float_as_uint(wb[ci]);
                uint32_t b1 = __float_as_uint(wb[ci + 4 * 264]);
                mma_tf32(acc2[0][nt], a00, a01, a02, a03, b0, b1);
                mma_tf32(acc2[1][nt], a10, a11, a12, a13, b0, b1);
            }
            if (t < 7) {
                *(float4*)(sm + W2S + (buf ^ 1) * 2112 + kr2 * 264 + c42 * 4) = cvt4(q0);
                *(float4*)(sm + W2S + (buf ^ 1) * 2112 + (kr2 + 4) * 264 + c42 * 4) = cvt4(q1);
            }
            __syncthreads();
        }
    }

    // ---------------- epilogue ----------------
    {
        float* ob = out + ((size_t)head * 8192 + n0) * 256;
        #pragma unroll
        for (int mt = 0; mt < 2; mt++)
            #pragma unroll
            for (int nt = 0; nt < 8; nt++) {
                int r = wm * 32 + mt * 16 + g;
                int c = wn * 64 + nt * 8 + 2 * tg;
                *(float2*)(ob + (size_t)r * 256 + c) =
                    make_float2(acc2[mt][nt][0], acc2[mt][nt][1]);
                *(float2*)(ob + (size_t)(r + 8) * 256 + c) =
                    make_float2(acc2[mt][nt][2], acc2[mt][nt][3]);
            }
    }
}

extern "C" void kernel_launch(void* const* d_in, const int* in_sizes, int n_in,
                              void* d_out, int out_size) {
    const float* x  = (const float*)d_in[0];
    const float* w1 = (const float*)d_in[1];
    const float* w2 = (const float*)d_in[2];
    float* out = (float*)d_out;

    cudaFuncSetAttribute(mlp_mma_v3,
                         cudaFuncAttributeMaxDynamicSharedMemorySize, SMEM_BYTES);

    dim3 grid(8192 / 64, 16);
    mlp_mma_v3<<<grid, NTH, SMEM_BYTES>>>(x, w1, w2, out);
}

// round 5
// speedup vs baseline: 1.9949x; 1.9949x over previous
#include <cuda_runtime.h>
#include <cuda_fp16.h>
#include <cstdint>

#define NTH 512

// Fragment-major fp16 weights in device scratch (uint4 = 4 b32 regs for one lane).
// W1F: (((h*16+ic)*16+ks)*4+ntp)*32 + lane   (ic = 64-col chunk of I, ks = k16 step over D)
// W2F: (((h*16+ic)*4+ks)*16+ntp)*32 + lane   (ic = 64-row chunk of I, ks = k16 step, n over D)
__device__ uint4 W1F[16*16*16*4*32];
__device__ uint4 W2F[16*16*4*16*32];

__device__ __forceinline__ uint32_t packh2(float a, float b) {
    __half2 h = __floats2half2_rn(a, b);
    return *reinterpret_cast<uint32_t*>(&h);
}
__device__ __forceinline__ float silu(float v) { return v / (1.0f + expf(-v)); }

// ---------------- weight prep kernels ----------------
__global__ void prep_w1(const float* __restrict__ w1) {
    __shared__ float tile[32][65];
    int b = blockIdx.x;
    int kh = b & 7, ic = (b >> 3) & 15, h = b >> 7;
    const float* src = w1 + ((size_t)h * 256 + kh * 32) * 1024 + ic * 64;
    int tid = threadIdx.x;
    #pragma unroll
    for (int j = 0; j < 2; j++) {
        int flat = tid + j * 256;            // float4 idx, 16 per row
        int r = flat >> 4, c4 = flat & 15;
        float4 v = *(const float4*)(src + (size_t)r * 1024 + c4 * 4);
        tile[r][c4*4+0] = v.x; tile[r][c4*4+1] = v.y;
        tile[r][c4*4+2] = v.z; tile[r][c4*4+3] = v.w;
    }
    __syncthreads();
    int lane = tid & 31, ntp = (tid >> 5) & 3, kso = tid >> 7;
    int gcol = lane >> 2, tg = lane & 3;
    int kb = kso * 16 + 2 * tg;
    int n  = ntp * 16 + gcol;
    uint4 o;
    o.x = packh2(tile[kb][n],     tile[kb+1][n]);
    o.y = packh2(tile[kb+8][n],   tile[kb+9][n]);
    o.z = packh2(tile[kb][n+8],   tile[kb+1][n+8]);
    o.w = packh2(tile[kb+8][n+8], tile[kb+9][n+8]);
    int ks = kh * 2 + kso;
    W1F[(((h*16 + ic)*16 + ks)*4 + ntp)*32 + lane] = o;
}

__global__ void prep_w2(const float* __restrict__ w2) {
    __shared__ float tile[16][257];
    int b = blockIdx.x;
    int ks = b & 3, ic = (b >> 2) & 15, h = b >> 6;
    const float* src = w2 + ((size_t)h * 1024 + ic * 64 + ks * 16) * 256;
    int tid = threadIdx.x;
    #pragma unroll
    for (int j = 0; j < 4; j++) {
        int flat = tid + j * 256;            // 64 float4 per row
        int r = flat >> 6, c4 = flat & 63;
        float4 v = *(const float4*)(src + (size_t)r * 256 + c4 * 4);
        tile[r][c4*4+0] = v.x; tile[r][c4*4+1] = v.y;
        tile[r][c4*4+2] = v.z; tile[r][c4*4+3] = v.w;
    }
    __syncthreads();
    #pragma unroll
    for (int j = 0; j < 2; j++) {
        int idx = tid + j * 256;             // 512 uint4 per block
        int lane = idx & 31, ntp = idx >> 5;
        int gcol = lane >> 2, tg = lane & 3;
        int kb = 2 * tg, n = ntp * 16 + gcol;
        uint4 o;
        o.x = packh2(tile[kb][n],     tile[kb+1][n]);
        o.y = packh2(tile[kb+8][n],   tile[kb+9][n]);
        o.z = packh2(tile[kb][n+8],   tile[kb+1][n+8]);
        o.w = packh2(tile[kb+8][n+8], tile[kb+9][n+8]);
        W2F[(((h*16 + ic)*4 + ks)*16 + ntp)*32 + lane] = o;
    }
}

// ---------------- main fused kernel ----------------
// SMEM (u32 units): XA[0,16384) x A-frags; HA[16384,20480) h A-frags;
// W1S[20480,24576) 2x2048; W2S[24576,32768) 2x4096. Total 128KB.
#define XA  0
#define HA  16384
#define W1S 20480
#define W2S 24576
#define SMEM_BYTES (32768 * 4)

__device__ __forceinline__ void mma16816(float* c, uint4 A, uint32_t b0, uint32_t b1) {
    asm volatile("mma.sync.aligned.m16n8k16.row.col.f32.f16.f16.f32 "
        "{%0,%1,%2,%3},{%4,%5,%6,%7},{%8,%9},{%0,%1,%2,%3};"
        : "+f"(c[0]), "+f"(c[1]), "+f"(c[2]), "+f"(c[3])
        : "r"(A.x), "r"(A.y), "r"(A.z), "r"(A.w), "r"(b0), "r"(b1));
}

__global__ __launch_bounds__(NTH, 1)
void mlp_fp16_main(const float* __restrict__ x, float* __restrict__ out) {
    extern __shared__ uint32_t sm[];
    const int tid  = threadIdx.x;
    const int lane = tid & 31, wid = tid >> 5;
    const int g = lane >> 2, tg = lane & 3;
    const int wm = wid >> 2, wn = wid & 3;
    const int head = blockIdx.y;
    const int n0 = blockIdx.x * 128;

    // ---- stage x[128x256] -> fp16 A-fragment-major ----
    {
        const float* xb = x + ((size_t)head * 8192 + n0) * 256;
        #pragma unroll
        for (int j = 0; j < 16; j++) {
            int idx = tid + j * NTH;         // float4 index, 64 per row
            int m = idx >> 6, c4 = idx & 63;
            float4 v = *(const float4*)(xb + (size_t)m * 256 + c4 * 4);
            int ks  = c4 >> 2;
            int hi  = (c4 >> 1) & 1;
            int tg0 = (c4 & 1) * 2;
            int mt = m >> 4, gg = m & 7, mhi = (m >> 3) & 1;
            int reg = hi * 2 + mhi;
            int base = XA + ((ks * 8 + mt) * 32 + gg * 4) * 4 + reg;
            sm[base + tg0 * 4]       = packh2(v.x, v.y);
            sm[base + (tg0 + 1) * 4] = packh2(v.z, v.w);
        }
    }
    __syncthreads();

    float acc2[2][8][4];
    #pragma unroll
    for (int mt = 0; mt < 2; mt++)
        #pragma unroll
        for (int nt = 0; nt < 8; nt++)
            #pragma unroll
            for (int r = 0; r < 4; r++) acc2[mt][nt][r] = 0.0f;

    const uint4* w1base0 = W1F + (size_t)(head * 16) * 2048;
    const uint4* w2base0 = W2F + (size_t)(head * 16) * 2048;

    #pragma unroll 1
    for (int ic = 0; ic < 16; ic++) {
        const uint4* w1base = w1base0 + (size_t)ic * 2048;
        const uint4* w2base = w2base0 + (size_t)ic * 2048;

        // ===== GEMM1: z[128x64] = x[128x256] @ w1[:, ic*64 : ic*64+64) =====
        float acc1[2][2][4];
        #pragma unroll
        for (int mt = 0; mt < 2; mt++)
            #pragma unroll
            for (int np = 0; np < 2; np++)
                #pragma unroll
                for (int r = 0; r < 4; r++) acc1[mt][np][r] = 0.0f;

        *(uint4*)(sm + W1S + tid * 4) = w1base[tid];   // preload slab 0
        __syncthreads();

        #pragma unroll
        for (int s = 0; s < 4; s++) {
            uint4 q;
            if (s < 3) q = w1base[(s + 1) * 512 + tid];
            const uint32_t* wb = sm + W1S + (s & 1) * 2048;
            #pragma unroll
            for (int kso = 0; kso < 4; kso++) {
                int ks = s * 4 + kso;
                uint4 A0 = *(const uint4*)(sm + XA + ((ks * 8 + wm * 2) * 32 + lane) * 4);
                uint4 A1 = *(const uint4*)(sm + XA + ((ks * 8 + wm * 2 + 1) * 32 + lane) * 4);
                uint4 B  = *(const uint4*)(wb + (kso * 4 + wn) * 128 + lane * 4);
                mma16816(acc1[0][0], A0, B.x, B.y);
                mma16816(acc1[0][1], A0, B.z, B.w);
                mma16816(acc1[1][0], A1, B.x, B.y);
                mma16816(acc1[1][1], A1, B.z, B.w);
            }
            if (s < 3) *(uint4*)(sm + W1S + ((s + 1) & 1) * 2048 + tid * 4) = q;
            __syncthreads();
        }

        // ---- silu -> h A-fragments; preload w2 slab 0 in parallel ----
        uint4 p0 = w2base[tid];
        uint4 p1 = w2base[tid + 512];
        #pragma unroll
        for (int mt = 0; mt < 2; mt++)
            #pragma unroll
            for (int np = 0; np < 2; np++) {
                uint2 hv;
                hv.x = packh2(silu(acc1[mt][np][0]), silu(acc1[mt][np][1]));
                hv.y = packh2(silu(acc1[mt][np][2]), silu(acc1[mt][np][3]));
                *(uint2*)(sm + HA + ((wn * 8 + wm * 2 + mt) * 32 + lane) * 4 + np * 2) = hv;
            }
        *(uint4*)(sm + W2S + tid * 4) = p0;
        *(uint4*)(sm + W2S + (tid + 512) * 4) = p1;
        __syncthreads();

        // ===== GEMM2: o[128x256] += h[128x64] @ w2[ic*64 : +64, :) =====
        #pragma unroll
        for (int t = 0; t < 2; t++) {
            uint4 q0, q1;
            if (t < 1) { q0 = w2base[1024 + tid]; q1 = w2base[1024 + tid + 512]; }
            const uint32_t* wb = sm + W2S + (t & 1) * 4096;
            #pragma unroll
            for (int kso = 0; kso < 2; kso++) {
                int ks = t * 2 + kso;
                uint4 A0 = *(const uint4*)(sm + HA + ((ks * 8 + wm * 2) * 32 + lane) * 4);
                uint4 A1 = *(const uint4*)(sm + HA + ((ks * 8 + wm * 2 + 1) * 32 + lane) * 4);
                #pragma unroll
                for (int np = 0; np < 4; np++) {
                    uint4 B = *(const uint4*)(wb + (kso * 16 + wn * 4 + np) * 128 + lane * 4);
                    mma16816(acc2[0][np * 2],     A0, B.x, B.y);
                    mma16816(acc2[0][np * 2 + 1], A0, B.z, B.w);
                    mma16816(acc2[1][np * 2],     A1, B.x, B.y);
                    mma16816(acc2[1][np * 2 + 1], A1, B.z, B.w);
                }
            }
            if (t < 1) {
                *(uint4*)(sm + W2S + 4096 + tid * 4) = q0;
                *(uint4*)(sm + W2S + 4096 + (tid + 512) * 4) = q1;
            }
            __syncthreads();
        }
    }

    // ---- epilogue: acc2 -> out (f32) ----
    {
        float* ob = out + ((size_t)head * 8192 + n0 + wm * 32 + g) * 256 + wn * 64 + 2 * tg;
        #pragma unroll
        for (int mt = 0; mt < 2; mt++)
            #pragma unroll
            for (int nt = 0; nt < 8; nt++) {
                *(float2*)(ob + (size_t)(mt * 16) * 256 + nt * 8) =
                    make_float2(acc2[mt][nt][0], acc2[mt][nt][1]);
                *(float2*)(ob + (size_t)(mt * 16 + 8) * 256 + nt * 8) =
                    make_float2(acc2[mt][nt][2], acc2[mt][nt][3]);
            }
    }
}

extern "C" void kernel_launch(void* const* d_in, const int* in_sizes, int n_in,
                              void* d_out, int out_size) {
    const float* x  = (const float*)d_in[0];
    const float* w1 = (const float*)d_in[1];
    const float* w2 = (const float*)d_in[2];
    float* out = (float*)d_out;

    prep_w1<<<2048, 256>>>(w1);
    prep_w2<<<1024, 256>>>(w2);

    cudaFuncSetAttribute(mlp_fp16_main,
                         cudaFuncAttributeMaxDynamicSharedMemorySize, SMEM_BYTES);
    dim3 grid(8192 / 128, 16);
    mlp_fp16_main<<<grid, NTH, SMEM_BYTES>>>(x, out);
}

// round 6
// speedup vs baseline: 2.3262x; 1.1661x over previous
#include <cuda_runtime.h>
#include <cuda_fp16.h>
#include <cstdint>

#define NTH 512

// Fragment-major fp16 weights in device scratch (uint4 = one lane's B fragment pair).
// W1F: (((h*16+ic)*16+ks)*4+ntp)*32 + lane
// W2F: (((h*16+ic)*4+ks)*16+ntp)*32 + lane
__device__ uint4 W1F[16*16*16*4*32];
__device__ uint4 W2F[16*16*4*16*32];

__device__ __forceinline__ uint32_t packh2(float a, float b) {
    __half2 h = __floats2half2_rn(a, b);
    return *reinterpret_cast<uint32_t*>(&h);
}
__device__ __forceinline__ float silu(float v) { return v / (1.0f + expf(-v)); }

// ---------------- weight prep kernels (unchanged from R5) ----------------
__global__ void prep_w1(const float* __restrict__ w1) {
    __shared__ float tile[32][65];
    int b = blockIdx.x;
    int kh = b & 7, ic = (b >> 3) & 15, h = b >> 7;
    const float* src = w1 + ((size_t)h * 256 + kh * 32) * 1024 + ic * 64;
    int tid = threadIdx.x;
    #pragma unroll
    for (int j = 0; j < 2; j++) {
        int flat = tid + j * 256;
        int r = flat >> 4, c4 = flat & 15;
        float4 v = *(const float4*)(src + (size_t)r * 1024 + c4 * 4);
        tile[r][c4*4+0] = v.x; tile[r][c4*4+1] = v.y;
        tile[r][c4*4+2] = v.z; tile[r][c4*4+3] = v.w;
    }
    __syncthreads();
    int lane = tid & 31, ntp = (tid >> 5) & 3, kso = tid >> 7;
    int gcol = lane >> 2, tg = lane & 3;
    int kb = kso * 16 + 2 * tg;
    int n  = ntp * 16 + gcol;
    uint4 o;
    o.x = packh2(tile[kb][n],     tile[kb+1][n]);
    o.y = packh2(tile[kb+8][n],   tile[kb+9][n]);
    o.z = packh2(tile[kb][n+8],   tile[kb+1][n+8]);
    o.w = packh2(tile[kb+8][n+8], tile[kb+9][n+8]);
    int ks = kh * 2 + kso;
    W1F[(((h*16 + ic)*16 + ks)*4 + ntp)*32 + lane] = o;
}

__global__ void prep_w2(const float* __restrict__ w2) {
    __shared__ float tile[16][257];
    int b = blockIdx.x;
    int ks = b & 3, ic = (b >> 2) & 15, h = b >> 6;
    const float* src = w2 + ((size_t)h * 1024 + ic * 64 + ks * 16) * 256;
    int tid = threadIdx.x;
    #pragma unroll
    for (int j = 0; j < 4; j++) {
        int flat = tid + j * 256;
        int r = flat >> 6, c4 = flat & 63;
        float4 v = *(const float4*)(src + (size_t)r * 256 + c4 * 4);
        tile[r][c4*4+0] = v.x; tile[r][c4*4+1] = v.y;
        tile[r][c4*4+2] = v.z; tile[r][c4*4+3] = v.w;
    }
    __syncthreads();
    #pragma unroll
    for (int j = 0; j < 2; j++) {
        int idx = tid + j * 256;
        int lane = idx & 31, ntp = idx >> 5;
        int gcol = lane >> 2, tg = lane & 3;
        int kb = 2 * tg, n = ntp * 16 + gcol;
        uint4 o;
        o.x = packh2(tile[kb][n],     tile[kb+1][n]);
        o.y = packh2(tile[kb+8][n],   tile[kb+9][n]);
        o.z = packh2(tile[kb][n+8],   tile[kb+1][n+8]);
        o.w = packh2(tile[kb+8][n+8], tile[kb+9][n+8]);
        W2F[(((h*16 + ic)*4 + ks)*16 + ntp)*32 + lane] = o;
    }
}

// ---------------- main fused kernel ----------------
// SMEM (u32 units): XA[0,16384) x A-frags; HA[16384,20480) h A-frags. Total 80KB.
#define XA  0
#define HA  16384
#define SMEM_BYTES (20480 * 4)

__device__ __forceinline__ void mma16816(float* c, uint4 A, uint32_t b0, uint32_t b1) {
    asm volatile("mma.sync.aligned.m16n8k16.row.col.f32.f16.f16.f32 "
        "{%0,%1,%2,%3},{%4,%5,%6,%7},{%8,%9},{%0,%1,%2,%3};"
        : "+f"(c[0]), "+f"(c[1]), "+f"(c[2]), "+f"(c[3])
        : "r"(A.x), "r"(A.y), "r"(A.z), "r"(A.w), "r"(b0), "r"(b1));
}

__global__ __launch_bounds__(NTH, 1)
void mlp_fp16_main(const float* __restrict__ x, float* __restrict__ out) {
    extern __shared__ uint32_t sm[];
    const int tid  = threadIdx.x;
    const int lane = tid & 31, wid = tid >> 5;
    const int g = lane >> 2, tg = lane & 3;
    const int wm = wid >> 2, wn = wid & 3;
    const int head = blockIdx.y;
    const int n0 = blockIdx.x * 128;

    // ---- stage x[128x256] -> fp16 A-fragment-major ----
    {
        const float* xb = x + ((size_t)head * 8192 + n0) * 256;
        #pragma unroll
        for (int j = 0; j < 16; j++) {
            int idx = tid + j * NTH;
            int m = idx >> 6, c4 = idx & 63;
            float4 v = *(const float4*)(xb + (size_t)m * 256 + c4 * 4);
            int ks  = c4 >> 2;
            int hi  = (c4 >> 1) & 1;
            int tg0 = (c4 & 1) * 2;
            int mt = m >> 4, gg = m & 7, mhi = (m >> 3) & 1;
            int reg = hi * 2 + mhi;
            int base = XA + ((ks * 8 + mt) * 32 + gg * 4) * 4 + reg;
            sm[base + tg0 * 4]       = packh2(v.x, v.y);
            sm[base + (tg0 + 1) * 4] = packh2(v.z, v.w);
        }
    }
    __syncthreads();

    float acc2[2][8][4];
    #pragma unroll
    for (int mt = 0; mt < 2; mt++)
        #pragma unroll
        for (int nt = 0; nt < 8; nt++)
            #pragma unroll
            for (int r = 0; r < 4; r++) acc2[mt][nt][r] = 0.0f;

    const uint4* w1base0 = W1F + (size_t)(head * 16) * 2048;
    const uint4* w2base0 = W2F + (size_t)(head * 16) * 2048;

    #pragma unroll 1
    for (int ic = 0; ic < 16; ic++) {
        // B pointers for this chunk (lane-resolved)
        const uint4* bp = w1base0 + (size_t)ic * 2048 + wn * 32 + lane;        // + ks*128
        const uint4* bq = w2base0 + (size_t)ic * 2048 + wn * 4 * 32 + lane;    // + ks*512 + np*32

        // ===== GEMM1: z[128x64] = x[128x256] @ w1 chunk  (B direct from L2) =====
        float acc1[2][2][4];
        #pragma unroll
        for (int mt = 0; mt < 2; mt++)
            #pragma unroll
            for (int np = 0; np < 2; np++)
                #pragma unroll
                for (int r = 0; r < 4; r++) acc1[mt][np][r] = 0.0f;

        uint4 B0 = bp[0];
        uint4 B1 = bp[128];
        #pragma unroll
        for (int ks = 0; ks < 16; ks++) {
            uint4 B2;
            if (ks < 14) B2 = bp[(ks + 2) * 128];
            uint4 A0 = *(const uint4*)(sm + XA + ((ks * 8 + wm * 2) * 32 + lane) * 4);
            uint4 A1 = *(const uint4*)(sm + XA + ((ks * 8 + wm * 2 + 1) * 32 + lane) * 4);
            mma16816(acc1[0][0], A0, B0.x, B0.y);
            mma16816(acc1[0][1], A0, B0.z, B0.w);
            mma16816(acc1[1][0], A1, B0.x, B0.y);
            mma16816(acc1[1][1], A1, B0.z, B0.w);
            B0 = B1; B1 = B2;
        }

        __syncthreads();   // all warps done reading HA from previous ic's GEMM2

        // ---- silu -> h A-fragments ----
        #pragma unroll
        for (int mt = 0; mt < 2; mt++)
            #pragma unroll
            for (int np = 0; np < 2; np++) {
                uint2 hv;
                hv.x = packh2(silu(acc1[mt][np][0]), silu(acc1[mt][np][1]));
                hv.y = packh2(silu(acc1[mt][np][2]), silu(acc1[mt][np][3]));
                *(uint2*)(sm + HA + ((wn * 8 + wm * 2 + mt) * 32 + lane) * 4 + np * 2) = hv;
            }

        // prefetch GEMM2 ks=0 B fragments while waiting at the barrier
        uint4 C0 = bq[0];
        uint4 C1 = bq[32];
        uint4 C2 = bq[64];
        uint4 C3 = bq[96];

        __syncthreads();   // HA visible to all warps

        // ===== GEMM2: o[128x256] += h[128x64] @ w2 chunk (B direct from L2) =====
        #pragma unroll
        for (int ks = 0; ks < 4; ks++) {
            uint4 D0, D1, D2, D3;
            if (ks < 3) {
                D0 = bq[(ks + 1) * 512];
                D1 = bq[(ks + 1) * 512 + 32];
                D2 = bq[(ks + 1) * 512 + 64];
                D3 = bq[(ks + 1) * 512 + 96];
            }
            uint4 A0 = *(const uint4*)(sm + HA + ((ks * 8 + wm * 2) * 32 + lane) * 4);
            uint4 A1 = *(const uint4*)(sm + HA + ((ks * 8 + wm * 2 + 1) * 32 + lane) * 4);
            mma16816(acc2[0][0], A0, C0.x, C0.y);
            mma16816(acc2[0][1], A0, C0.z, C0.w);
            mma16816(acc2[1][0], A1, C0.x, C0.y);
            mma16816(acc2[1][1], A1, C0.z, C0.w);
            mma16816(acc2[0][2], A0, C1.x, C1.y);
            mma16816(acc2[0][3], A0, C1.z, C1.w);
            mma16816(acc2[1][2], A1, C1.x, C1.y);
            mma16816(acc2[1][3], A1, C1.z, C1.w);
            mma16816(acc2[0][4], A0, C2.x, C2.y);
            mma16816(acc2[0][5], A0, C2.z, C2.w);
            mma16816(acc2[1][4], A1, C2.x, C2.y);
            mma16816(acc2[1][5], A1, C2.z, C2.w);
            mma16816(acc2[0][6], A0, C3.x, C3.y);
            mma16816(acc2[0][7], A0, C3.z, C3.w);
            mma16816(acc2[1][6], A1, C3.x, C3.y);
            mma16816(acc2[1][7], A1, C3.z, C3.w);
            C0 = D0; C1 = D1; C2 = D2; C3 = D3;
        }
    }

    // ---- epilogue: acc2 -> out (f32) ----
    {
        float* ob = out + ((size_t)head * 8192 + n0 + wm * 32 + g) * 256 + wn * 64 + 2 * tg;
        #pragma unroll
        for (int mt = 0; mt < 2; mt++)
            #pragma unroll
            for (int nt = 0; nt < 8; nt++) {
                *(float2*)(ob + (size_t)(mt * 16) * 256 + nt * 8) =
                    make_float2(acc2[mt][nt][0], acc2[mt][nt][1]);
                *(float2*)(ob + (size_t)(mt * 16 + 8) * 256 + nt * 8) =
                    make_float2(acc2[mt][nt][2], acc2[mt][nt][3]);
            }
    }
}

extern "C" void kernel_launch(void* const* d_in, const int* in_sizes, int n_in,
                              void* d_out, int out_size) {
    const float* x  = (const float*)d_in[0];
    const float* w1 = (const float*)d_in[1];
    const float* w2 = (const float*)d_in[2];
    float* out = (float*)d_out;

    prep_w1<<<2048, 256>>>(w1);
    prep_w2<<<1024, 256>>>(w2);

    cudaFuncSetAttribute(mlp_fp16_main,
                         cudaFuncAttributeMaxDynamicSharedMemorySize, SMEM_BYTES);
    dim3 grid(8192 / 128, 16);
    mlp_fp16_main<<<grid, NTH, SMEM_BYTES>>>(x, out);
}

// round 7
// speedup vs baseline: 2.3532x; 1.0116x over previous
#include <cuda_runtime.h>
#include <cuda_fp16.h>
#include <cstdint>

#define NTH 512

// Fragment-major fp16 weights in device scratch (uint4 = one lane's B fragment pair).
// W1F: (((h*16+ic)*16+ks)*4+ntp)*32 + lane
// W2F: (((h*16+ic)*4+ks)*16+ntp)*32 + lane
__device__ uint4 W1F[16*16*16*4*32];
__device__ uint4 W2F[16*16*4*16*32];

__device__ __forceinline__ uint32_t packh2(float a, float b) {
    __half2 h = __floats2half2_rn(a, b);
    return *reinterpret_cast<uint32_t*>(&h);
}
__device__ __forceinline__ float silu(float v) { return v / (1.0f + expf(-v)); }

// ---------------- merged weight prep kernel ----------------
// blocks [0,2048): w1 tiles; blocks [2048,3072): w2 tiles
__global__ void prep_w(const float* __restrict__ w1, const float* __restrict__ w2) {
    __shared__ float tile[16 * 257];   // w1 uses 32x65 view, w2 uses 16x257 view
    int tid = threadIdx.x;
    if (blockIdx.x < 2048) {
        int b = blockIdx.x;
        int kh = b & 7, ic = (b >> 3) & 15, h = b >> 7;
        const float* src = w1 + ((size_t)h * 256 + kh * 32) * 1024 + ic * 64;
        #pragma unroll
        for (int j = 0; j < 2; j++) {
            int flat = tid + j * 256;
            int r = flat >> 4, c4 = flat & 15;
            float4 v = *(const float4*)(src + (size_t)r * 1024 + c4 * 4);
            tile[r*65 + c4*4+0] = v.x; tile[r*65 + c4*4+1] = v.y;
            tile[r*65 + c4*4+2] = v.z; tile[r*65 + c4*4+3] = v.w;
        }
        __syncthreads();
        int lane = tid & 31, ntp = (tid >> 5) & 3, kso = tid >> 7;
        int gcol = lane >> 2, tg = lane & 3;
        int kb = kso * 16 + 2 * tg;
        int n  = ntp * 16 + gcol;
        uint4 o;
        o.x = packh2(tile[kb*65 + n],       tile[(kb+1)*65 + n]);
        o.y = packh2(tile[(kb+8)*65 + n],   tile[(kb+9)*65 + n]);
        o.z = packh2(tile[kb*65 + n+8],     tile[(kb+1)*65 + n+8]);
        o.w = packh2(tile[(kb+8)*65 + n+8], tile[(kb+9)*65 + n+8]);
        int ks = kh * 2 + kso;
        W1F[(((h*16 + ic)*16 + ks)*4 + ntp)*32 + lane] = o;
    } else {
        int b = blockIdx.x - 2048;
        int ks = b & 3, ic = (b >> 2) & 15, h = b >> 6;
        const float* src = w2 + ((size_t)h * 1024 + ic * 64 + ks * 16) * 256;
        #pragma unroll
        for (int j = 0; j < 4; j++) {
            int flat = tid + j * 256;
            int r = flat >> 6, c4 = flat & 63;
            float4 v = *(const float4*)(src + (size_t)r * 256 + c4 * 4);
            tile[r*257 + c4*4+0] = v.x; tile[r*257 + c4*4+1] = v.y;
            tile[r*257 + c4*4+2] = v.z; tile[r*257 + c4*4+3] = v.w;
        }
        __syncthreads();
        #pragma unroll
        for (int j = 0; j < 2; j++) {
            int idx = tid + j * 256;
            int lane = idx & 31, ntp = idx >> 5;
            int gcol = lane >> 2, tg = lane & 3;
            int kb = 2 * tg, n = ntp * 16 + gcol;
            uint4 o;
            o.x = packh2(tile[kb*257 + n],       tile[(kb+1)*257 + n]);
            o.y = packh2(tile[(kb+8)*257 + n],   tile[(kb+9)*257 + n]);
            o.z = packh2(tile[kb*257 + n+8],     tile[(kb+1)*257 + n+8]);
            o.w = packh2(tile[(kb+8)*257 + n+8], tile[(kb+9)*257 + n+8]);
            W2F[(((h*16 + ic)*4 + ks)*16 + ntp)*32 + lane] = o;
        }
    }
}

// ---------------- main fused kernel ----------------
// SMEM (u32): XA[0,16384) x A-frags; HA0[16384,20480); HA1[20480,24576). 96KB.
#define XA  0
#define HA0 16384
#define HA1 20480
#define SMEM_BYTES (24576 * 4)

__device__ __forceinline__ void mma16816(float* c, uint4 A, uint32_t b0, uint32_t b1) {
    asm volatile("mma.sync.aligned.m16n8k16.row.col.f32.f16.f16.f32 "
        "{%0,%1,%2,%3},{%4,%5,%6,%7},{%8,%9},{%0,%1,%2,%3};"
        : "+f"(c[0]), "+f"(c[1]), "+f"(c[2]), "+f"(c[3])
        : "r"(A.x), "r"(A.y), "r"(A.z), "r"(A.w), "r"(b0), "r"(b1));
}

__global__ __launch_bounds__(NTH, 1)
void mlp_fp16_main(const float* __restrict__ x, float* __restrict__ out) {
    extern __shared__ uint32_t sm[];
    const int tid  = threadIdx.x;
    const int lane = tid & 31, wid = tid >> 5;
    const int g = lane >> 2, tg = lane & 3;
    const int wm = wid >> 2, wn = wid & 3;
    const int head = blockIdx.y;
    const int n0 = blockIdx.x * 128;

    // ---- stage x[128x256] -> fp16 A-fragment-major ----
    {
        const float* xb = x + ((size_t)head * 8192 + n0) * 256;
        #pragma unroll
        for (int j = 0; j < 16; j++) {
            int idx = tid + j * NTH;
            int m = idx >> 6, c4 = idx & 63;
            float4 v = *(const float4*)(xb + (size_t)m * 256 + c4 * 4);
            int ks  = c4 >> 2;
            int hi  = (c4 >> 1) & 1;
            int tg0 = (c4 & 1) * 2;
            int mt = m >> 4, gg = m & 7, mhi = (m >> 3) & 1;
            int reg = hi * 2 + mhi;
            int base = XA + ((ks * 8 + mt) * 32 + gg * 4) * 4 + reg;
            sm[base + tg0 * 4]       = packh2(v.x, v.y);
            sm[base + (tg0 + 1) * 4] = packh2(v.z, v.w);
        }
    }
    __syncthreads();

    float acc2[2][8][4];
    #pragma unroll
    for (int mt = 0; mt < 2; mt++)
        #pragma unroll
        for (int nt = 0; nt < 8; nt++)
            #pragma unroll
            for (int r = 0; r < 4; r++) acc2[mt][nt][r] = 0.0f;

    const uint4* w1base0 = W1F + (size_t)(head * 16) * 2048;
    const uint4* w2base0 = W2F + (size_t)(head * 16) * 2048;

    #pragma unroll 1
    for (int ic = 0; ic < 16; ic++) {
        const uint4* bp = w1base0 + (size_t)ic * 2048 + wn * 32 + lane;
        const uint4* bq = w2base0 + (size_t)ic * 2048 + wn * 4 * 32 + lane;
        uint32_t* ha = sm + ((ic & 1) ? HA1 : HA0);

        // ===== GEMM1: z[128x64] = x[128x256] @ w1 chunk (B direct from L2) =====
        float acc1[2][2][4];
        #pragma unroll
        for (int mt = 0; mt < 2; mt++)
            #pragma unroll
            for (int np = 0; np < 2; np++)
                #pragma unroll
                for (int r = 0; r < 4; r++) acc1[mt][np][r] = 0.0f;

        uint4 B0 = bp[0];
        uint4 B1 = bp[128];
        uint4 B2 = bp[256];
        #pragma unroll
        for (int ks = 0; ks < 16; ks++) {
            uint4 B3;
            if (ks < 13) B3 = bp[(ks + 3) * 128];
            uint4 A0 = *(const uint4*)(sm + XA + ((ks * 8 + wm * 2) * 32 + lane) * 4);
            uint4 A1 = *(const uint4*)(sm + XA + ((ks * 8 + wm * 2 + 1) * 32 + lane) * 4);
            mma16816(acc1[0][0], A0, B0.x, B0.y);
            mma16816(acc1[0][1], A0, B0.z, B0.w);
            mma16816(acc1[1][0], A1, B0.x, B0.y);
            mma16816(acc1[1][1], A1, B0.z, B0.w);
            B0 = B1; B1 = B2; B2 = B3;
        }

        // ---- silu -> h A-fragments (double-buffered HA; no pre-barrier needed:
        //      barrier(ic-1) already separates all warps' GEMM2(ic-2) reads) ----
        #pragma unroll
        for (int mt = 0; mt < 2; mt++)
            #pragma unroll
            for (int np = 0; np < 2; np++) {
                uint2 hv;
                hv.x = packh2(silu(acc1[mt][np][0]), silu(acc1[mt][np][1]));
                hv.y = packh2(silu(acc1[mt][np][2]), silu(acc1[mt][np][3]));
                *(uint2*)(ha + ((wn * 8 + wm * 2 + mt) * 32 + lane) * 4 + np * 2) = hv;
            }

        // prefetch GEMM2 ks=0 B fragments while waiting at the barrier
        uint4 C0 = bq[0];
        uint4 C1 = bq[32];
        uint4 C2 = bq[64];
        uint4 C3 = bq[96];

        __syncthreads();   // HA visible to all warps

        // ===== GEMM2: o[128x256] += h[128x64] @ w2 chunk (B direct from L2) =====
        #pragma unroll
        for (int ks = 0; ks < 4; ks++) {
            uint4 D0, D1, D2, D3;
            if (ks < 3) {
                D0 = bq[(ks + 1) * 512];
                D1 = bq[(ks + 1) * 512 + 32];
                D2 = bq[(ks + 1) * 512 + 64];
                D3 = bq[(ks + 1) * 512 + 96];
            }
            uint4 A0 = *(const uint4*)(ha + ((ks * 8 + wm * 2) * 32 + lane) * 4);
            uint4 A1 = *(const uint4*)(ha + ((ks * 8 + wm * 2 + 1) * 32 + lane) * 4);
            mma16816(acc2[0][0], A0, C0.x, C0.y);
            mma16816(acc2[0][1], A0, C0.z, C0.w);
            mma16816(acc2[1][0], A1, C0.x, C0.y);
            mma16816(acc2[1][1], A1, C0.z, C0.w);
            mma16816(acc2[0][2], A0, C1.x, C1.y);
            mma16816(acc2[0][3], A0, C1.z, C1.w);
            mma16816(acc2[1][2], A1, C1.x, C1.y);
            mma16816(acc2[1][3], A1, C1.z, C1.w);
            mma16816(acc2[0][4], A0, C2.x, C2.y);
            mma16816(acc2[0][5], A0, C2.z, C2.w);
            mma16816(acc2[1][4], A1, C2.x, C2.y);
            mma16816(acc2[1][5], A1, C2.z, C2.w);
            mma16816(acc2[0][6], A0, C3.x, C3.y);
            mma16816(acc2[0][7], A0, C3.z, C3.w);
            mma16816(acc2[1][6], A1, C3.x, C3.y);
            mma16816(acc2[1][7], A1, C3.z, C3.w);
            C0 = D0; C1 = D1; C2 = D2; C3 = D3;
        }
    }

    // ---- epilogue: acc2 -> out (f32) ----
    {
        float* ob = out + ((size_t)head * 8192 + n0 + wm * 32 + g) * 256 + wn * 64 + 2 * tg;
        #pragma unroll
        for (int mt = 0; mt < 2; mt++)
            #pragma unroll
            for (int nt = 0; nt < 8; nt++) {
                *(float2*)(ob + (size_t)(mt * 16) * 256 + nt * 8) =
                    make_float2(acc2[mt][nt][0], acc2[mt][nt][1]);
                *(float2*)(ob + (size_t)(mt * 16 + 8) * 256 + nt * 8) =
                    make_float2(acc2[mt][nt][2], acc2[mt][nt][3]);
            }
    }
}

extern "C" void kernel_launch(void* const* d_in, const int* in_sizes, int n_in,
                              void* d_out, int out_size) {
    const float* x  = (const float*)d_in[0];
    const float* w1 = (const float*)d_in[1];
    const float* w2 = (const float*)d_in[2];
    float* out = (float*)d_out;

    prep_w<<<3072, 256>>>(w1, w2);

    cudaFuncSetAttribute(mlp_fp16_main,
                         cudaFuncAttributeMaxDynamicSharedMemorySize, SMEM_BYTES);
    dim3 grid(8192 / 128, 16);
    mlp_fp16_main<<<grid, NTH, SMEM_BYTES>>>(x, out);
}